// round 10
// baseline (speedup 1.0000x reference)
#include <cuda_runtime.h>
#include <cuda_fp16.h>
#include <math.h>
#include <stdint.h>

#define T_TOK 2048
#define H_DIM 2048
#define E_NUM 32
#define I_DIM 768
#define TOPK  8
#define NASSIGN (T_TOK * TOPK)

// ---------------- scratch ----------------
__device__ int   g_topk_id[T_TOK][TOPK];
__device__ float g_topk_w[T_TOK][TOPK];
__device__ int   g_cnt[E_NUM];
__device__ int   g_off[E_NUM + 1];
__device__ int   g_slot_tok[NASSIGN];
__device__ float g_slot_w[NASSIGN];
__device__ __half g_hs_h[(size_t)T_TOK * H_DIM];
__device__ __half g_act_h[NASSIGN][I_DIM];

// ---------------- PTX helpers ----------------
__device__ __forceinline__ void mma16816(float* d, const uint32_t* a, const uint32_t* b) {
    asm volatile(
        "mma.sync.aligned.m16n8k16.row.col.f32.f16.f16.f32 "
        "{%0,%1,%2,%3}, {%4,%5,%6,%7}, {%8,%9}, {%0,%1,%2,%3};"
        : "+f"(d[0]), "+f"(d[1]), "+f"(d[2]), "+f"(d[3])
        : "r"(a[0]), "r"(a[1]), "r"(a[2]), "r"(a[3]), "r"(b[0]), "r"(b[1]));
}
#define LDMX4(r, addr) \
    asm volatile("ldmatrix.sync.aligned.m8n8.x4.shared.b16 {%0,%1,%2,%3}, [%4];" \
        : "=r"((r)[0]), "=r"((r)[1]), "=r"((r)[2]), "=r"((r)[3]) : "r"(addr))
#define CP16(dst, src) \
    asm volatile("cp.async.cg.shared.global [%0], [%1], 16;" :: "r"(dst), "l"(src))
#define CP_COMMIT() asm volatile("cp.async.commit_group;" ::: "memory")
#define CP_WAIT1()  asm volatile("cp.async.wait_group 1;" ::: "memory")
#define CP_WAIT0()  asm volatile("cp.async.wait_group 0;" ::: "memory")

__device__ __forceinline__ uint32_t smem_u32(const void* p) {
    return (uint32_t)__cvta_generic_to_shared(p);
}
// 8 fp32 (two float4) -> uint4 of packed fp16x2
__device__ __forceinline__ uint4 pack8h(const float4& v0, const float4& v1) {
    __half2 h0 = __floats2half2_rn(v0.x, v0.y);
    __half2 h1 = __floats2half2_rn(v0.z, v0.w);
    __half2 h2 = __floats2half2_rn(v1.x, v1.y);
    __half2 h3 = __floats2half2_rn(v1.z, v1.w);
    uint4 o;
    o.x = *(uint32_t*)&h0; o.y = *(uint32_t*)&h1;
    o.z = *(uint32_t*)&h2; o.w = *(uint32_t*)&h3;
    return o;
}

// ---------------- hidden convert: fp32 -> fp16 (+ zero g_cnt) ---------------
__global__ void conv_hs_kernel(const float* __restrict__ hs) {
    if (blockIdx.x == 0 && threadIdx.x < E_NUM) g_cnt[threadIdx.x] = 0;
    size_t total8 = (size_t)T_TOK * H_DIM / 8;
    for (size_t i = (size_t)blockIdx.x * blockDim.x + threadIdx.x; i < total8;
         i += (size_t)gridDim.x * blockDim.x) {
        const float* src = hs + i * 8;
        float4 v0 = *(const float4*)src;
        float4 v1 = *(const float4*)(src + 4);
        *(uint4*)&g_hs_h[i * 8] = pack8h(v0, v1);
    }
}

// ---------------- router ----------------
__global__ void router_kernel(const float* __restrict__ hs, const float* __restrict__ gw) {
    int t = blockIdx.x;
    __shared__ float part[128][E_NUM];
    __shared__ float sl[E_NUM];
    float acc[E_NUM];
#pragma unroll
    for (int e = 0; e < E_NUM; e++) acc[e] = 0.f;
    const float* hrow = hs + (size_t)t * H_DIM;
    for (int h = threadIdx.x; h < H_DIM; h += 128) {
        float x = hrow[h];
#pragma unroll
        for (int e = 0; e < E_NUM; e++) acc[e] += x * gw[e * H_DIM + h];
    }
#pragma unroll
    for (int e = 0; e < E_NUM; e++) part[threadIdx.x][e] = acc[e];
    __syncthreads();
    if (threadIdx.x < E_NUM) {
        float s = 0.f;
        for (int i = 0; i < 128; i++) s += part[i][threadIdx.x];
        sl[threadIdx.x] = s;
    }
    __syncthreads();
    if (threadIdx.x == 0) {
        unsigned mask = 0;
        int ids[TOPK]; float lv[TOPK];
        for (int k = 0; k < TOPK; k++) {
            float best = -3.4e38f; int bi = 0;
            for (int e = 0; e < E_NUM; e++)
                if (!((mask >> e) & 1u) && sl[e] > best) { best = sl[e]; bi = e; }
            mask |= (1u << bi); ids[k] = bi; lv[k] = best;
        }
        float mx = lv[0], s = 0.f, w[TOPK];
        for (int k = 0; k < TOPK; k++) { w[k] = expf(lv[k] - mx); s += w[k]; }
        float inv = 1.f / s;
        for (int k = 0; k < TOPK; k++) {
            g_topk_id[t][k] = ids[k];
            g_topk_w[t][k]  = w[k] * inv;
            atomicAdd(&g_cnt[ids[k]], 1);
        }
    }
}

// ---------------- fused scan + scatter ----------------
__global__ void dispatch_kernel() {
    __shared__ int soff[E_NUM];
    __shared__ int scur[E_NUM];
    int tid = threadIdx.x;
    if (tid < E_NUM) scur[tid] = 0;
    if (tid == 0) {
        int s = 0;
        for (int e = 0; e < E_NUM; e++) { g_off[e] = s; soff[e] = s; s += g_cnt[e]; }
        g_off[E_NUM] = s;
    }
    __syncthreads();
    for (int t = tid; t < T_TOK; t += 256) {
#pragma unroll
        for (int k = 0; k < TOPK; k++) {
            int e = g_topk_id[t][k];
            int p = atomicAdd(&scur[e], 1);
            int s = soff[e] + p;
            g_slot_tok[s] = t;
            g_slot_w[s]  = g_topk_w[t][k];
        }
    }
}

// ===== gate-up GEMM: A fp16 cp.async (3-stage), B fp32 inline convert =======
// stage (bytes): A 0 (128x80=10240) | B_G 10240 (64x80=5120) | B_U 15360
#define GU_STAGE 20480
#define GU_META  (3 * GU_STAGE)
#define GU_SMEM  (GU_META + 1024)
#define GU_NCH   (H_DIM / 32)

__global__ __launch_bounds__(256, 2) void gateup_mma_kernel(
    const float* __restrict__ wg, const float* __restrict__ wu)
{
    int e = blockIdx.z;
    int cnt = g_cnt[e];
    int m0 = blockIdx.y * 128;
    if (m0 >= cnt) return;
    int base = g_off[e];
    int n0 = blockIdx.x * 64;

    extern __shared__ char smem[];
    uint32_t sb = smem_u32(smem);
    int tid = threadIdx.x, wid = tid >> 5, lane = tid & 31;
    int g = lane >> 2, t4 = lane & 3;

    int*   stok = (int*)(smem + GU_META);
    float* swt  = (float*)(smem + GU_META + 512);
    if (tid < 128) {
        int r = m0 + tid;
        int rc = (r < cnt) ? r : (cnt - 1);
        stok[tid] = g_slot_tok[base + rc];
        swt[tid]  = (r < cnt) ? g_slot_w[base + rc] : 0.f;
    }
    __syncthreads();

    // A: cp.async fp16, 2 thr/row, 32B each
    int lr = tid >> 1, asel = tid & 1;
    const __half* a_src = g_hs_h + (size_t)stok[lr] * H_DIM + asel * 16;
    uint32_t aDst = sb + (uint32_t)(lr * 80 + asel * 32);
    // B: fp32 inline convert. 4 thr/row over 64 rows; each thread does 8 fp32
    // of BOTH gate and up.
    int brow = tid >> 2, bq = tid & 3;
    const float* bg_src = wg + ((size_t)e * I_DIM + n0 + brow) * H_DIM + bq * 8;
    const float* bu_src = wu + ((size_t)e * I_DIM + n0 + brow) * H_DIM + bq * 8;
    uint32_t bDstG = sb + 10240u + (uint32_t)(brow * 80 + bq * 16);
    uint32_t bDstU = bDstG + 5120u;

    // fragment addressing
    int quad = lane >> 3, r8 = lane & 7;
    int aRow = (quad & 1) * 8 + r8, aCol = (quad >> 1) * 8;
    int bRow = (quad >> 1) * 8 + r8, bCol = (quad & 1) * 8;
    int mr = (wid & 3) * 32, nc = (wid >> 2) * 32;
    uint32_t aBase = sb + (uint32_t)((mr + aRow) * 80 + aCol * 2);
    uint32_t bBase = sb + 10240u + (uint32_t)((nc + bRow) * 80 + bCol * 2);

    float ag[2][4][4] = {}, au[2][4][4] = {};
    float4 rg[2], ru[2];   // B register prefetch

#define GU_ISSUE_A(i) do { \
    uint32_t so = (uint32_t)((i) % 3) * GU_STAGE; \
    int k0 = (i) * 32; \
    CP16(aDst + so,      (const char*)(a_src + k0)); \
    CP16(aDst + so + 16, (const char*)(a_src + k0 + 8)); \
    CP_COMMIT(); \
} while (0)
#define GU_LDG_B(i) do { \
    int k0 = (i) * 32; \
    rg[0] = *(const float4*)(bg_src + k0);     rg[1] = *(const float4*)(bg_src + k0 + 4); \
    ru[0] = *(const float4*)(bu_src + k0);     ru[1] = *(const float4*)(bu_src + k0 + 4); \
} while (0)
#define GU_STS_B(i) do { \
    uint32_t so = (uint32_t)((i) % 3) * GU_STAGE; \
    *(uint4*)(smem + (bDstG - sb) + so) = pack8h(rg[0], rg[1]); \
    *(uint4*)(smem + (bDstU - sb) + so) = pack8h(ru[0], ru[1]); \
} while (0)

    // prologue: stages 0,1 fully staged; chunk2 B in regs
    GU_ISSUE_A(0); GU_ISSUE_A(1);
    GU_LDG_B(0); GU_STS_B(0);
    GU_LDG_B(1); GU_STS_B(1);
    GU_LDG_B(2);

    for (int i = 0; i < GU_NCH; i++) {
        if (i + 1 < GU_NCH) CP_WAIT1(); else CP_WAIT0();
        __syncthreads();
        if (i + 2 < GU_NCH) { GU_ISSUE_A(i + 2); GU_STS_B(i + 2); }
        if (i + 3 < GU_NCH) GU_LDG_B(i + 3);
        uint32_t so = (uint32_t)(i % 3) * GU_STAGE;
#pragma unroll
        for (int kb = 0; kb < 2; kb++) {
            uint32_t aH[2][4];
            uint32_t aA = aBase + so + kb * 32;
            LDMX4(aH[0], aA);
            LDMX4(aH[1], aA + 16 * 80);
#pragma unroll
            for (int p = 0; p < 2; p++) {
                uint32_t bg[4], bu[4];
                uint32_t bA = bBase + so + p * 16 * 80 + kb * 32;
                LDMX4(bg, bA);
                LDMX4(bu, bA + 5120);
#pragma unroll
                for (int s = 0; s < 2; s++) {
                    mma16816(ag[s][2 * p + 0], aH[s], bg);
                    mma16816(ag[s][2 * p + 1], aH[s], bg + 2);
                    mma16816(au[s][2 * p + 0], aH[s], bu);
                    mma16816(au[s][2 * p + 1], aH[s], bu + 2);
                }
            }
        }
        __syncthreads();
    }

    // epilogue: silu(g)*u*route_w -> fp16 act scratch
#pragma unroll
    for (int s = 0; s < 2; s++) {
#pragma unroll
        for (int half = 0; half < 2; half++) {
            int rl = mr + s * 16 + g + half * 8;
            int r = m0 + rl;
            if (r < cnt) {
                float w = swt[rl];
                size_t slot = (size_t)(base + r);
#pragma unroll
                for (int nn = 0; nn < 4; nn++) {
                    float gv0 = ag[s][nn][half * 2 + 0], gv1 = ag[s][nn][half * 2 + 1];
                    float uv0 = au[s][nn][half * 2 + 0], uv1 = au[s][nn][half * 2 + 1];
                    float a0 = (gv0 / (1.f + expf(-gv0))) * uv0 * w;
                    float a1 = (gv1 / (1.f + expf(-gv1))) * uv1 * w;
                    __half2 hp = __floats2half2_rn(a0, a1);
                    int col = n0 + nc + nn * 8 + 2 * t4;
                    *(uint32_t*)&g_act_h[slot][col] = *(uint32_t*)&hp;
                }
            }
        }
    }
#undef GU_ISSUE_A
#undef GU_LDG_B
#undef GU_STS_B
}

// ===== down GEMM: A fp16 cp.async (3-stage), B fp32 inline convert ==========
// stage: A 0 (10240) | B 10240 (5120) ; STAGE 15360
#define DN_STAGE 15360
#define DN_META  (3 * DN_STAGE)
#define DN_SMEM  (DN_META + 512)
#define DN_NCH   (I_DIM / 32)

__global__ __launch_bounds__(256, 2) void down_mma_kernel(
    const float* __restrict__ wd, float* __restrict__ out)
{
    int e = blockIdx.z;
    int cnt = g_cnt[e];
    int m0 = blockIdx.y * 128;
    if (m0 >= cnt) return;
    int base = g_off[e];
    int n0 = blockIdx.x * 64;

    extern __shared__ char smem[];
    uint32_t sb = smem_u32(smem);
    int tid = threadIdx.x, wid = tid >> 5, lane = tid & 31;
    int g = lane >> 2, t4 = lane & 3;

    int* stok = (int*)(smem + DN_META);
    if (tid < 128) {
        int r = m0 + tid;
        stok[tid] = (r < cnt) ? g_slot_tok[base + r] : 0;
    }
    __syncthreads();

    int lr = tid >> 1, asel = tid & 1;
    int arow_idx = base + min(m0 + lr, cnt - 1);
    const __half* a_src = &g_act_h[arow_idx][asel * 16];
    uint32_t aDst = sb + (uint32_t)(lr * 80 + asel * 32);
    int brow = tid >> 2, bq = tid & 3;
    const float* b_src = wd + ((size_t)e * H_DIM + n0 + brow) * I_DIM + bq * 8;
    uint32_t bDst = sb + 10240u + (uint32_t)(brow * 80 + bq * 16);

    int quad = lane >> 3, r8 = lane & 7;
    int aRow = (quad & 1) * 8 + r8, aCol = (quad >> 1) * 8;
    int bRow = (quad >> 1) * 8 + r8, bCol = (quad & 1) * 8;
    int mr = (wid & 3) * 32, nc = (wid >> 2) * 32;
    uint32_t aBase = sb + (uint32_t)((mr + aRow) * 80 + aCol * 2);
    uint32_t bBase = sb + 10240u + (uint32_t)((nc + bRow) * 80 + bCol * 2);

    float dd[2][4][4] = {};
    float4 rb[2];

#define DN_ISSUE_A(i) do { \
    uint32_t so = (uint32_t)((i) % 3) * DN_STAGE; \
    int k0 = (i) * 32; \
    CP16(aDst + so,      (const char*)(a_src + k0)); \
    CP16(aDst + so + 16, (const char*)(a_src + k0 + 8)); \
    CP_COMMIT(); \
} while (0)
#define DN_LDG_B(i) do { \
    int k0 = (i) * 32; \
    rb[0] = *(const float4*)(b_src + k0); \
    rb[1] = *(const float4*)(b_src + k0 + 4); \
} while (0)
#define DN_STS_B(i) do { \
    uint32_t so = (uint32_t)((i) % 3) * DN_STAGE; \
    *(uint4*)(smem + (bDst - sb) + so) = pack8h(rb[0], rb[1]); \
} while (0)

    DN_ISSUE_A(0); DN_ISSUE_A(1);
    DN_LDG_B(0); DN_STS_B(0);
    DN_LDG_B(1); DN_STS_B(1);
    DN_LDG_B(2);

    for (int i = 0; i < DN_NCH; i++) {
        if (i + 1 < DN_NCH) CP_WAIT1(); else CP_WAIT0();
        __syncthreads();
        if (i + 2 < DN_NCH) { DN_ISSUE_A(i + 2); DN_STS_B(i + 2); }
        if (i + 3 < DN_NCH) DN_LDG_B(i + 3);
        uint32_t so = (uint32_t)(i % 3) * DN_STAGE;
#pragma unroll
        for (int kb = 0; kb < 2; kb++) {
            uint32_t aH[2][4];
            uint32_t aA = aBase + so + kb * 32;
            LDMX4(aH[0], aA);
            LDMX4(aH[1], aA + 16 * 80);
#pragma unroll
            for (int p = 0; p < 2; p++) {
                uint32_t bh[4];
                uint32_t bA = bBase + so + p * 16 * 80 + kb * 32;
                LDMX4(bh, bA);
#pragma unroll
                for (int s = 0; s < 2; s++) {
                    mma16816(dd[s][2 * p + 0], aH[s], bh);
                    mma16816(dd[s][2 * p + 1], aH[s], bh + 2);
                }
            }
        }
        __syncthreads();
    }

    // epilogue: atomic accumulate
#pragma unroll
    for (int s = 0; s < 2; s++) {
#pragma unroll
        for (int half = 0; half < 2; half++) {
            int rl = mr + s * 16 + g + half * 8;
            int r = m0 + rl;
            if (r < cnt) {
                int tok = stok[rl];
#pragma unroll
                for (int nn = 0; nn < 4; nn++) {
                    int col = n0 + nc + nn * 8 + 2 * t4;
                    float* orow = out + (size_t)tok * H_DIM + col;
                    atomicAdd(&orow[0], dd[s][nn][half * 2 + 0]);
                    atomicAdd(&orow[1], dd[s][nn][half * 2 + 1]);
                }
            }
        }
    }
#undef DN_ISSUE_A
#undef DN_LDG_B
#undef DN_STS_B
}

// ---------------- launch ----------------
extern "C" void kernel_launch(void* const* d_in, const int* in_sizes, int n_in,
                              void* d_out, int out_size) {
    const float* hs    = (const float*)d_in[0];
    const float* gw    = (const float*)d_in[1];
    const float* wgate = (const float*)d_in[2];
    const float* wup   = (const float*)d_in[3];
    const float* wdown = (const float*)d_in[4];
    float* out = (float*)d_out;

    cudaFuncSetAttribute(gateup_mma_kernel, cudaFuncAttributeMaxDynamicSharedMemorySize, GU_SMEM);
    cudaFuncSetAttribute(down_mma_kernel,   cudaFuncAttributeMaxDynamicSharedMemorySize, DN_SMEM);

    cudaMemsetAsync(d_out, 0, (size_t)out_size * sizeof(float));
    conv_hs_kernel<<<512, 256>>>(hs);
    router_kernel<<<T_TOK, 128>>>(hs, gw);
    dispatch_kernel<<<1, 256>>>();
    gateup_mma_kernel<<<dim3(I_DIM / 64, T_TOK / 128, E_NUM), 256, GU_SMEM>>>(wgate, wup);
    down_mma_kernel  <<<dim3(H_DIM / 64, T_TOK / 128, E_NUM), 256, DN_SMEM>>>(wdown, out);
}

// round 11
// speedup vs baseline: 1.2756x; 1.2756x over previous
#include <cuda_runtime.h>
#include <cuda_fp16.h>
#include <math.h>
#include <stdint.h>

#define T_TOK 2048
#define H_DIM 2048
#define E_NUM 32
#define I_DIM 768
#define TOPK  8
#define NASSIGN (T_TOK * TOPK)
#define NW ((size_t)E_NUM * I_DIM * H_DIM)

// ---------------- scratch ----------------
__device__ int   g_topk_id[T_TOK][TOPK];
__device__ float g_topk_w[T_TOK][TOPK];
__device__ int   g_cnt[E_NUM];
__device__ int   g_off[E_NUM + 1];
__device__ int   g_slot_tok[NASSIGN];
__device__ float g_slot_w[NASSIGN];
__device__ __half g_wg_h[NW];
__device__ __half g_wu_h[NW];
__device__ __half g_wd_h[NW];
__device__ __half g_hs_h[(size_t)T_TOK * H_DIM];
__device__ __half g_act_h[NASSIGN][I_DIM];

// ---------------- PTX helpers ----------------
__device__ __forceinline__ void mma16816(float* d, const uint32_t* a, const uint32_t* b) {
    asm volatile(
        "mma.sync.aligned.m16n8k16.row.col.f32.f16.f16.f32 "
        "{%0,%1,%2,%3}, {%4,%5,%6,%7}, {%8,%9}, {%0,%1,%2,%3};"
        : "+f"(d[0]), "+f"(d[1]), "+f"(d[2]), "+f"(d[3])
        : "r"(a[0]), "r"(a[1]), "r"(a[2]), "r"(a[3]), "r"(b[0]), "r"(b[1]));
}
#define LDMX4(r, addr) \
    asm volatile("ldmatrix.sync.aligned.m8n8.x4.shared.b16 {%0,%1,%2,%3}, [%4];" \
        : "=r"((r)[0]), "=r"((r)[1]), "=r"((r)[2]), "=r"((r)[3]) : "r"(addr))
#define CP16(dst, src) \
    asm volatile("cp.async.cg.shared.global [%0], [%1], 16;" :: "r"(dst), "l"(src))
#define CP_COMMIT() asm volatile("cp.async.commit_group;" ::: "memory")
#define CP_WAIT1()  asm volatile("cp.async.wait_group 1;" ::: "memory")
#define CP_WAIT0()  asm volatile("cp.async.wait_group 0;" ::: "memory")

__device__ __forceinline__ uint32_t smem_u32(const void* p) {
    return (uint32_t)__cvta_generic_to_shared(p);
}
__device__ __forceinline__ uint4 pack8h(const float4& v0, const float4& v1) {
    __half2 h0 = __floats2half2_rn(v0.x, v0.y);
    __half2 h1 = __floats2half2_rn(v0.z, v0.w);
    __half2 h2 = __floats2half2_rn(v1.x, v1.y);
    __half2 h3 = __floats2half2_rn(v1.z, v1.w);
    uint4 o;
    o.x = *(uint32_t*)&h0; o.y = *(uint32_t*)&h1;
    o.z = *(uint32_t*)&h2; o.w = *(uint32_t*)&h3;
    return o;
}

// ---------------- weight convert: fp32 -> fp16 ----------------
__global__ void conv_w_kernel(const float* __restrict__ wg,
                              const float* __restrict__ wu,
                              const float* __restrict__ wd) {
    size_t total8 = (3 * NW) / 8;
    for (size_t i = (size_t)blockIdx.x * blockDim.x + threadIdx.x; i < total8;
         i += (size_t)gridDim.x * blockDim.x) {
        size_t e8 = i * 8;
        const float* src; __half* dst;
        if (e8 < NW)          { src = wg + e8;          dst = g_wg_h + e8; }
        else if (e8 < 2 * NW) { src = wu + (e8 - NW);   dst = g_wu_h + (e8 - NW); }
        else                  { src = wd + (e8 - 2*NW); dst = g_wd_h + (e8 - 2*NW); }
        float4 v0 = *(const float4*)src;
        float4 v1 = *(const float4*)(src + 4);
        *(uint4*)dst = pack8h(v0, v1);
    }
}

// ---------------- hidden convert (+ zero g_cnt) ----------------
__global__ void conv_hs_kernel(const float* __restrict__ hs) {
    if (blockIdx.x == 0 && threadIdx.x < E_NUM) g_cnt[threadIdx.x] = 0;
    size_t total8 = (size_t)T_TOK * H_DIM / 8;
    for (size_t i = (size_t)blockIdx.x * blockDim.x + threadIdx.x; i < total8;
         i += (size_t)gridDim.x * blockDim.x) {
        const float* src = hs + i * 8;
        float4 v0 = *(const float4*)src;
        float4 v1 = *(const float4*)(src + 4);
        *(uint4*)&g_hs_h[i * 8] = pack8h(v0, v1);
    }
}

// ---------------- router ----------------
__global__ void router_kernel(const float* __restrict__ hs, const float* __restrict__ gw) {
    int t = blockIdx.x;
    __shared__ float part[128][E_NUM];
    __shared__ float sl[E_NUM];
    float acc[E_NUM];
#pragma unroll
    for (int e = 0; e < E_NUM; e++) acc[e] = 0.f;
    const float* hrow = hs + (size_t)t * H_DIM;
    for (int h = threadIdx.x; h < H_DIM; h += 128) {
        float x = hrow[h];
#pragma unroll
        for (int e = 0; e < E_NUM; e++) acc[e] += x * gw[e * H_DIM + h];
    }
#pragma unroll
    for (int e = 0; e < E_NUM; e++) part[threadIdx.x][e] = acc[e];
    __syncthreads();
    if (threadIdx.x < E_NUM) {
        float s = 0.f;
        for (int i = 0; i < 128; i++) s += part[i][threadIdx.x];
        sl[threadIdx.x] = s;
    }
    __syncthreads();
    if (threadIdx.x == 0) {
        unsigned mask = 0;
        int ids[TOPK]; float lv[TOPK];
        for (int k = 0; k < TOPK; k++) {
            float best = -3.4e38f; int bi = 0;
            for (int e = 0; e < E_NUM; e++)
                if (!((mask >> e) & 1u) && sl[e] > best) { best = sl[e]; bi = e; }
            mask |= (1u << bi); ids[k] = bi; lv[k] = best;
        }
        float mx = lv[0], s = 0.f, w[TOPK];
        for (int k = 0; k < TOPK; k++) { w[k] = expf(lv[k] - mx); s += w[k]; }
        float inv = 1.f / s;
        for (int k = 0; k < TOPK; k++) {
            g_topk_id[t][k] = ids[k];
            g_topk_w[t][k]  = w[k] * inv;
            atomicAdd(&g_cnt[ids[k]], 1);
        }
    }
}

// ---------------- fused scan + scatter ----------------
__global__ void dispatch_kernel() {
    __shared__ int soff[E_NUM];
    __shared__ int scur[E_NUM];
    int tid = threadIdx.x;
    if (tid < E_NUM) scur[tid] = 0;
    if (tid == 0) {
        int s = 0;
        for (int e = 0; e < E_NUM; e++) { g_off[e] = s; soff[e] = s; s += g_cnt[e]; }
        g_off[E_NUM] = s;
    }
    __syncthreads();
    for (int t = tid; t < T_TOK; t += 256) {
#pragma unroll
        for (int k = 0; k < TOPK; k++) {
            int e = g_topk_id[t][k];
            int p = atomicAdd(&scur[e], 1);
            int s = soff[e] + p;
            g_slot_tok[s] = t;
            g_slot_w[s]  = g_topk_w[t][k];
        }
    }
}

// ====== gate-up GEMM: 128 thr, 4 warps x (64x64), smem up-exchange ==========
// stage: A[128][80]=10240 | B_G[64][80]=5120 | B_U 15360..20480 ; STAGE 20480
#define GU_STAGE 20480
#define GU_META  (3 * GU_STAGE)
#define GU_SMEM  (GU_META + 1024)
#define GU_NCH   (H_DIM / 32)
#define XCH_PITCH 72                      // floats; 64 rows x 72 x 4B = 18432 B / warp

__global__ __launch_bounds__(128, 2) void gateup_mma_kernel() {
    int e = blockIdx.z;
    int cnt = g_cnt[e];
    int m0 = blockIdx.y * 128;
    if (m0 >= cnt) return;
    int base = g_off[e];
    int n0 = blockIdx.x * 64;

    extern __shared__ char smem[];
    uint32_t sb = smem_u32(smem);
    int tid = threadIdx.x, wid = tid >> 5, lane = tid & 31;
    int g = lane >> 2, t4 = lane & 3;
    int matSel = wid >> 1;                // 0 = gate, 1 = up
    int mr = (wid & 1) * 64;              // warp M offset

    int*   stok = (int*)(smem + GU_META);
    float* swt  = (float*)(smem + GU_META + 512);
    {
        int r = m0 + tid;
        int rc = (r < cnt) ? r : (cnt - 1);
        stok[tid] = g_slot_tok[base + rc];
        swt[tid]  = (r < cnt) ? g_slot_w[base + rc] : 0.f;
    }
    __syncthreads();

    // A loader: 1 thr/row, 64B per chunk
    const __half* a_src = g_hs_h + (size_t)stok[tid] * H_DIM;
    uint32_t aDst = sb + (uint32_t)(tid * 80);
    // B loader: rows 0..63 of gate (tid<64) or up (tid>=64), 64B per chunk
    int bmat = tid >> 6, brow = tid & 63;
    const __half* b_src = (bmat ? g_wu_h : g_wg_h)
                          + ((size_t)e * I_DIM + n0 + brow) * H_DIM;
    uint32_t bDst = sb + 10240u + (uint32_t)bmat * 5120u + (uint32_t)(brow * 80);

    // fragment addressing
    int quad = lane >> 3, r8 = lane & 7;
    int aRow = (quad & 1) * 8 + r8, aCol = (quad >> 1) * 8;
    int bRow = (quad >> 1) * 8 + r8, bCol = (quad & 1) * 8;
    uint32_t aBase = sb + (uint32_t)((mr + aRow) * 80 + aCol * 2);
    uint32_t bBase = sb + 10240u + (uint32_t)matSel * 5120u
                        + (uint32_t)(bRow * 80 + bCol * 2);

    float acc[4][8][4] = {};              // 64x64 output per warp

#define GU_ISSUE(i) do { \
    uint32_t so = (uint32_t)((i) % 3) * GU_STAGE; \
    int k0 = (i) * 32; \
    CP16(aDst + so,      (const char*)(a_src + k0)); \
    CP16(aDst + so + 16, (const char*)(a_src + k0 + 8)); \
    CP16(aDst + so + 32, (const char*)(a_src + k0 + 16)); \
    CP16(aDst + so + 48, (const char*)(a_src + k0 + 24)); \
    CP16(bDst + so,      (const char*)(b_src + k0)); \
    CP16(bDst + so + 16, (const char*)(b_src + k0 + 8)); \
    CP16(bDst + so + 32, (const char*)(b_src + k0 + 16)); \
    CP16(bDst + so + 48, (const char*)(b_src + k0 + 24)); \
    CP_COMMIT(); \
} while (0)

    GU_ISSUE(0);
    GU_ISSUE(1);

    for (int i = 0; i < GU_NCH; i++) {
        if (i + 1 < GU_NCH) CP_WAIT1(); else CP_WAIT0();
        __syncthreads();
        if (i + 2 < GU_NCH) GU_ISSUE(i + 2);
        uint32_t so = (uint32_t)(i % 3) * GU_STAGE;
#pragma unroll
        for (int kb = 0; kb < 2; kb++) {
            uint32_t aF[4][4], bF[4][4];
#pragma unroll
            for (int t = 0; t < 4; t++) LDMX4(aF[t], aBase + so + t * 1280 + kb * 32);
#pragma unroll
            for (int u = 0; u < 4; u++) LDMX4(bF[u], bBase + so + u * 1280 + kb * 32);
#pragma unroll
            for (int t = 0; t < 4; t++)
#pragma unroll
                for (int u = 0; u < 4; u++) {
                    mma16816(acc[t][2 * u + 0], aF[t], bF[u]);
                    mma16816(acc[t][2 * u + 1], aF[t], bF[u] + 2);
                }
        }
        __syncthreads();
    }
#undef GU_ISSUE

    // ---- epilogue: up warps publish acc via smem; gate warps combine ----
    float* xch = (float*)smem;            // reuse stage area (all MMA reads done)
    if (matSel == 1) {
        float* reg = xch + (wid & 1) * (64 * XCH_PITCH);
#pragma unroll
        for (int t = 0; t < 4; t++)
#pragma unroll
            for (int h = 0; h < 2; h++) {
                int lm = t * 16 + g + h * 8;
#pragma unroll
                for (int nn = 0; nn < 8; nn++) {
                    *(float2*)&reg[lm * XCH_PITCH + nn * 8 + 2 * t4] =
                        make_float2(acc[t][nn][h * 2 + 0], acc[t][nn][h * 2 + 1]);
                }
            }
    }
    __syncthreads();
    if (matSel == 0) {
        float* reg = xch + (wid & 1) * (64 * XCH_PITCH);
#pragma unroll
        for (int t = 0; t < 4; t++)
#pragma unroll
            for (int h = 0; h < 2; h++) {
                int lm = t * 16 + g + h * 8;
                int r = m0 + mr + lm;
                if (r < cnt) {
                    float w = swt[mr + lm];
                    size_t slot = (size_t)(base + r);
#pragma unroll
                    for (int nn = 0; nn < 8; nn++) {
                        float2 uv = *(float2*)&reg[lm * XCH_PITCH + nn * 8 + 2 * t4];
                        float gv0 = acc[t][nn][h * 2 + 0], gv1 = acc[t][nn][h * 2 + 1];
                        float a0 = (gv0 / (1.f + expf(-gv0))) * uv.x * w;
                        float a1 = (gv1 / (1.f + expf(-gv1))) * uv.y * w;
                        __half2 hp = __floats2half2_rn(a0, a1);
                        int col = n0 + nn * 8 + 2 * t4;
                        *(uint32_t*)&g_act_h[slot][col] = *(uint32_t*)&hp;
                    }
                }
            }
    }
}

// ====== down GEMM: 128 thr, CTA 128x128, 4 warps x (64x64) ==================
// stage: A[128][80]=10240 | B[128][80]=10240 ; STAGE 20480
#define DN_STAGE 20480
#define DN_META  (3 * DN_STAGE)
#define DN_SMEM  (DN_META + 512)
#define DN_NCH   (I_DIM / 32)

__global__ __launch_bounds__(128, 2) void down_mma_kernel(float* __restrict__ out) {
    int e = blockIdx.z;
    int cnt = g_cnt[e];
    int m0 = blockIdx.y * 128;
    if (m0 >= cnt) return;
    int base = g_off[e];
    int n0 = blockIdx.x * 128;

    extern __shared__ char smem[];
    uint32_t sb = smem_u32(smem);
    int tid = threadIdx.x, wid = tid >> 5, lane = tid & 31;
    int g = lane >> 2, t4 = lane & 3;
    int mr = (wid & 1) * 64, nc = (wid >> 1) * 64;

    int* stok = (int*)(smem + DN_META);
    {
        int r = m0 + tid;
        stok[tid] = (r < cnt) ? g_slot_tok[base + r] : 0;
    }
    __syncthreads();

    int arow_idx = base + min(m0 + tid, cnt - 1);
    const __half* a_src = g_act_h[arow_idx];
    uint32_t aDst = sb + (uint32_t)(tid * 80);
    const __half* b_src = g_wd_h + ((size_t)e * H_DIM + n0 + tid) * I_DIM;
    uint32_t bDst = sb + 10240u + (uint32_t)(tid * 80);

    int quad = lane >> 3, r8 = lane & 7;
    int aRow = (quad & 1) * 8 + r8, aCol = (quad >> 1) * 8;
    int bRow = (quad >> 1) * 8 + r8, bCol = (quad & 1) * 8;
    uint32_t aBase = sb + (uint32_t)((mr + aRow) * 80 + aCol * 2);
    uint32_t bBase = sb + 10240u + (uint32_t)((nc + bRow) * 80 + bCol * 2);

    float acc[4][8][4] = {};

#define DN_ISSUE(i) do { \
    uint32_t so = (uint32_t)((i) % 3) * DN_STAGE; \
    int k0 = (i) * 32; \
    CP16(aDst + so,      (const char*)(a_src + k0)); \
    CP16(aDst + so + 16, (const char*)(a_src + k0 + 8)); \
    CP16(aDst + so + 32, (const char*)(a_src + k0 + 16)); \
    CP16(aDst + so + 48, (const char*)(a_src + k0 + 24)); \
    CP16(bDst + so,      (const char*)(b_src + k0)); \
    CP16(bDst + so + 16, (const char*)(b_src + k0 + 8)); \
    CP16(bDst + so + 32, (const char*)(b_src + k0 + 16)); \
    CP16(bDst + so + 48, (const char*)(b_src + k0 + 24)); \
    CP_COMMIT(); \
} while (0)

    DN_ISSUE(0);
    DN_ISSUE(1);

    for (int i = 0; i < DN_NCH; i++) {
        if (i + 1 < DN_NCH) CP_WAIT1(); else CP_WAIT0();
        __syncthreads();
        if (i + 2 < DN_NCH) DN_ISSUE(i + 2);
        uint32_t so = (uint32_t)(i % 3) * DN_STAGE;
#pragma unroll
        for (int kb = 0; kb < 2; kb++) {
            uint32_t aF[4][4], bF[4][4];
#pragma unroll
            for (int t = 0; t < 4; t++) LDMX4(aF[t], aBase + so + t * 1280 + kb * 32);
#pragma unroll
            for (int u = 0; u < 4; u++) LDMX4(bF[u], bBase + so + u * 1280 + kb * 32);
#pragma unroll
            for (int t = 0; t < 4; t++)
#pragma unroll
                for (int u = 0; u < 4; u++) {
                    mma16816(acc[t][2 * u + 0], aF[t], bF[u]);
                    mma16816(acc[t][2 * u + 1], aF[t], bF[u] + 2);
                }
        }
        __syncthreads();
    }
#undef DN_ISSUE

    // epilogue: atomic accumulate
#pragma unroll
    for (int t = 0; t < 4; t++)
#pragma unroll
        for (int h = 0; h < 2; h++) {
            int lm = mr + t * 16 + g + h * 8;
            int r = m0 + lm;
            if (r < cnt) {
                int tok = stok[lm];
                float* orow = out + (size_t)tok * H_DIM + n0 + nc;
#pragma unroll
                for (int nn = 0; nn < 8; nn++) {
                    int col = nn * 8 + 2 * t4;
                    atomicAdd(&orow[col + 0], acc[t][nn][h * 2 + 0]);
                    atomicAdd(&orow[col + 1], acc[t][nn][h * 2 + 1]);
                }
            }
        }
}

// ---------------- launch ----------------
extern "C" void kernel_launch(void* const* d_in, const int* in_sizes, int n_in,
                              void* d_out, int out_size) {
    const float* hs    = (const float*)d_in[0];
    const float* gw    = (const float*)d_in[1];
    const float* wgate = (const float*)d_in[2];
    const float* wup   = (const float*)d_in[3];
    const float* wdown = (const float*)d_in[4];
    float* out = (float*)d_out;

    cudaFuncSetAttribute(gateup_mma_kernel, cudaFuncAttributeMaxDynamicSharedMemorySize, GU_SMEM);
    cudaFuncSetAttribute(down_mma_kernel,   cudaFuncAttributeMaxDynamicSharedMemorySize, DN_SMEM);

    cudaMemsetAsync(d_out, 0, (size_t)out_size * sizeof(float));
    conv_w_kernel<<<2048, 256>>>(wgate, wup, wdown);
    conv_hs_kernel<<<512, 256>>>(hs);
    router_kernel<<<T_TOK, 128>>>(hs, gw);
    dispatch_kernel<<<1, 256>>>();
    gateup_mma_kernel<<<dim3(I_DIM / 64, T_TOK / 128, E_NUM), 128, GU_SMEM>>>();
    down_mma_kernel  <<<dim3(H_DIM / 128, T_TOK / 128, E_NUM), 128, DN_SMEM>>>(out);
}

// round 12
// speedup vs baseline: 1.5645x; 1.2264x over previous
#include <cuda_runtime.h>
#include <cuda_fp16.h>
#include <math.h>
#include <stdint.h>

#define T_TOK 2048
#define H_DIM 2048
#define E_NUM 32
#define I_DIM 768
#define TOPK  8
#define NASSIGN (T_TOK * TOPK)
#define NW ((size_t)E_NUM * I_DIM * H_DIM)

// ---------------- scratch ----------------
__device__ int   g_topk_id[T_TOK][TOPK];
__device__ float g_topk_w[T_TOK][TOPK];
__device__ int   g_cnt[E_NUM];
__device__ int   g_off[E_NUM + 1];
__device__ int   g_cur[E_NUM];
__device__ int   g_slot_tok[NASSIGN];
__device__ float g_slot_w[NASSIGN];
__device__ __half g_wg_h[NW];
__device__ __half g_wu_h[NW];
__device__ __half g_wd_h[NW];
__device__ __half g_hs_h[(size_t)T_TOK * H_DIM];
__device__ __half g_act_h[NASSIGN][I_DIM];

// ---------------- PTX helpers ----------------
__device__ __forceinline__ void mma16816(float* d, const uint32_t* a, const uint32_t* b) {
    asm volatile(
        "mma.sync.aligned.m16n8k16.row.col.f32.f16.f16.f32 "
        "{%0,%1,%2,%3}, {%4,%5,%6,%7}, {%8,%9}, {%0,%1,%2,%3};"
        : "+f"(d[0]), "+f"(d[1]), "+f"(d[2]), "+f"(d[3])
        : "r"(a[0]), "r"(a[1]), "r"(a[2]), "r"(a[3]), "r"(b[0]), "r"(b[1]));
}
#define LDMX4(r, addr) \
    asm volatile("ldmatrix.sync.aligned.m8n8.x4.shared.b16 {%0,%1,%2,%3}, [%4];" \
        : "=r"((r)[0]), "=r"((r)[1]), "=r"((r)[2]), "=r"((r)[3]) : "r"(addr))
#define CP16(dst, src) \
    asm volatile("cp.async.cg.shared.global [%0], [%1], 16;" :: "r"(dst), "l"(src))
#define CP_COMMIT() asm volatile("cp.async.commit_group;" ::: "memory")
#define CP_WAIT1()  asm volatile("cp.async.wait_group 1;" ::: "memory")
#define CP_WAIT0()  asm volatile("cp.async.wait_group 0;" ::: "memory")

__device__ __forceinline__ uint32_t smem_u32(const void* p) {
    return (uint32_t)__cvta_generic_to_shared(p);
}
__device__ __forceinline__ uint4 pack8h(const float4& v0, const float4& v1) {
    __half2 h0 = __floats2half2_rn(v0.x, v0.y);
    __half2 h1 = __floats2half2_rn(v0.z, v0.w);
    __half2 h2 = __floats2half2_rn(v1.x, v1.y);
    __half2 h3 = __floats2half2_rn(v1.z, v1.w);
    uint4 o;
    o.x = *(uint32_t*)&h0; o.y = *(uint32_t*)&h1;
    o.z = *(uint32_t*)&h2; o.w = *(uint32_t*)&h3;
    return o;
}

// ------- fused convert: weights + hidden -> fp16, zero counters -------------
__global__ void conv_all_kernel(const float* __restrict__ wg,
                                const float* __restrict__ wu,
                                const float* __restrict__ wd,
                                const float* __restrict__ hs) {
    if (blockIdx.x == 0 && threadIdx.x < E_NUM) {
        g_cnt[threadIdx.x] = 0;
        g_cur[threadIdx.x] = 0;
    }
    size_t nhs = (size_t)T_TOK * H_DIM;
    size_t total8 = (3 * NW + nhs) / 8;
    for (size_t i = (size_t)blockIdx.x * blockDim.x + threadIdx.x; i < total8;
         i += (size_t)gridDim.x * blockDim.x) {
        size_t e8 = i * 8;
        const float* src; __half* dst;
        if (e8 < NW)          { src = wg + e8;           dst = g_wg_h + e8; }
        else if (e8 < 2 * NW) { src = wu + (e8 - NW);    dst = g_wu_h + (e8 - NW); }
        else if (e8 < 3 * NW) { src = wd + (e8 - 2*NW);  dst = g_wd_h + (e8 - 2*NW); }
        else                  { src = hs + (e8 - 3*NW);  dst = g_hs_h + (e8 - 3*NW); }
        float4 v0 = *(const float4*)src;
        float4 v1 = *(const float4*)(src + 4);
        *(uint4*)dst = pack8h(v0, v1);
    }
}

// ---------------- router ----------------
__global__ void router_kernel(const float* __restrict__ hs, const float* __restrict__ gw) {
    int t = blockIdx.x;
    __shared__ float part[128][E_NUM];
    __shared__ float sl[E_NUM];
    float acc[E_NUM];
#pragma unroll
    for (int e = 0; e < E_NUM; e++) acc[e] = 0.f;
    const float* hrow = hs + (size_t)t * H_DIM;
    for (int h = threadIdx.x; h < H_DIM; h += 128) {
        float x = hrow[h];
#pragma unroll
        for (int e = 0; e < E_NUM; e++) acc[e] += x * gw[e * H_DIM + h];
    }
#pragma unroll
    for (int e = 0; e < E_NUM; e++) part[threadIdx.x][e] = acc[e];
    __syncthreads();
    if (threadIdx.x < E_NUM) {
        float s = 0.f;
        for (int i = 0; i < 128; i++) s += part[i][threadIdx.x];
        sl[threadIdx.x] = s;
    }
    __syncthreads();
    if (threadIdx.x == 0) {
        unsigned mask = 0;
        int ids[TOPK]; float lv[TOPK];
        for (int k = 0; k < TOPK; k++) {
            float best = -3.4e38f; int bi = 0;
            for (int e = 0; e < E_NUM; e++)
                if (!((mask >> e) & 1u) && sl[e] > best) { best = sl[e]; bi = e; }
            mask |= (1u << bi); ids[k] = bi; lv[k] = best;
        }
        float mx = lv[0], s = 0.f, w[TOPK];
        for (int k = 0; k < TOPK; k++) { w[k] = expf(lv[k] - mx); s += w[k]; }
        float inv = 1.f / s;
        for (int k = 0; k < TOPK; k++) {
            g_topk_id[t][k] = ids[k];
            g_topk_w[t][k]  = w[k] * inv;
            atomicAdd(&g_cnt[ids[k]], 1);
        }
    }
}

// ---------------- scan (tiny) + parallel scatter ----------------
__global__ void scan_kernel() {
    if (threadIdx.x == 0) {
        int s = 0;
        for (int e = 0; e < E_NUM; e++) { g_off[e] = s; s += g_cnt[e]; }
        g_off[E_NUM] = s;
    }
}
__global__ void scatter_kernel() {
    int t = blockIdx.x * blockDim.x + threadIdx.x;
    if (t >= T_TOK) return;
#pragma unroll
    for (int k = 0; k < TOPK; k++) {
        int e = g_topk_id[t][k];
        int p = atomicAdd(&g_cur[e], 1);
        int s = g_off[e] + p;
        g_slot_tok[s] = t;
        g_slot_w[s]  = g_topk_w[t][k];
    }
}

// ============ gate-up GEMM: R9 config (256 thr, M128 N64, 3-stage) ==========
// stage (bytes): A 0 (128x80=10240) | B_G 10240 (64x80=5120) | B_U 15360
#define GU_STAGE 20480
#define GU_META  (3 * GU_STAGE)
#define GU_SMEM  (GU_META + 1024)
#define GU_NCH   (H_DIM / 32)

__global__ __launch_bounds__(256, 2) void gateup_mma_kernel() {
    int e = blockIdx.z;
    int cnt = g_cnt[e];
    int m0 = blockIdx.y * 128;
    if (m0 >= cnt) return;
    int base = g_off[e];
    int n0 = blockIdx.x * 64;

    extern __shared__ char smem[];
    uint32_t sb = smem_u32(smem);
    int tid = threadIdx.x, wid = tid >> 5, lane = tid & 31;
    int g = lane >> 2, t4 = lane & 3;

    int*   stok = (int*)(smem + GU_META);
    float* swt  = (float*)(smem + GU_META + 512);
    if (tid < 128) {
        int r = m0 + tid;
        int rc = (r < cnt) ? r : (cnt - 1);
        stok[tid] = g_slot_tok[base + rc];
        swt[tid]  = (r < cnt) ? g_slot_w[base + rc] : 0.f;
    }
    __syncthreads();

    int lr = tid >> 1, asel = tid & 1;
    const __half* a_src = g_hs_h + (size_t)stok[lr] * H_DIM + asel * 16;
    uint32_t aDst = sb + (uint32_t)(lr * 80 + asel * 32);
    int bt = tid & 127, br = bt >> 1, bsel = bt & 1;
    const __half* b_src = ((tid >= 128) ? g_wu_h : g_wg_h)
                          + ((size_t)e * I_DIM + n0 + br) * H_DIM + bsel * 16;
    uint32_t bDst = sb + 10240u + (tid >= 128 ? 5120u : 0u) + (uint32_t)(br * 80 + bsel * 32);

    int quad = lane >> 3, r8 = lane & 7;
    int aRow = (quad & 1) * 8 + r8, aCol = (quad >> 1) * 8;
    int bRow = (quad >> 1) * 8 + r8, bCol = (quad & 1) * 8;
    int mr = (wid & 3) * 32, nc = (wid >> 2) * 32;
    uint32_t aBase = sb + (uint32_t)((mr + aRow) * 80 + aCol * 2);
    uint32_t bBase = sb + 10240u + (uint32_t)((nc + bRow) * 80 + bCol * 2);

    float ag[2][4][4] = {}, au[2][4][4] = {};

#define GU_ISSUE(i) do { \
    uint32_t so = (uint32_t)((i) % 3) * GU_STAGE; \
    int k0 = (i) * 32; \
    CP16(aDst + so,      (const char*)(a_src + k0)); \
    CP16(aDst + so + 16, (const char*)(a_src + k0 + 8)); \
    CP16(bDst + so,      (const char*)(b_src + k0)); \
    CP16(bDst + so + 16, (const char*)(b_src + k0 + 8)); \
    CP_COMMIT(); \
} while (0)

    GU_ISSUE(0);
    GU_ISSUE(1);

    for (int i = 0; i < GU_NCH; i++) {
        if (i + 1 < GU_NCH) CP_WAIT1(); else CP_WAIT0();
        __syncthreads();
        if (i + 2 < GU_NCH) GU_ISSUE(i + 2);
        uint32_t so = (uint32_t)(i % 3) * GU_STAGE;
#pragma unroll
        for (int kb = 0; kb < 2; kb++) {
            uint32_t aH[2][4];
            uint32_t aA = aBase + so + kb * 32;
            LDMX4(aH[0], aA);
            LDMX4(aH[1], aA + 16 * 80);
#pragma unroll
            for (int p = 0; p < 2; p++) {
                uint32_t bg[4], bu[4];
                uint32_t bA = bBase + so + p * 16 * 80 + kb * 32;
                LDMX4(bg, bA);
                LDMX4(bu, bA + 5120);
#pragma unroll
                for (int s = 0; s < 2; s++) {
                    mma16816(ag[s][2 * p + 0], aH[s], bg);
                    mma16816(ag[s][2 * p + 1], aH[s], bg + 2);
                    mma16816(au[s][2 * p + 0], aH[s], bu);
                    mma16816(au[s][2 * p + 1], aH[s], bu + 2);
                }
            }
        }
        __syncthreads();
    }

#pragma unroll
    for (int s = 0; s < 2; s++) {
#pragma unroll
        for (int half = 0; half < 2; half++) {
            int rl = mr + s * 16 + g + half * 8;
            int r = m0 + rl;
            if (r < cnt) {
                float w = swt[rl];
                size_t slot = (size_t)(base + r);
#pragma unroll
                for (int nn = 0; nn < 4; nn++) {
                    float gv0 = ag[s][nn][half * 2 + 0], gv1 = ag[s][nn][half * 2 + 1];
                    float uv0 = au[s][nn][half * 2 + 0], uv1 = au[s][nn][half * 2 + 1];
                    float a0 = (gv0 / (1.f + expf(-gv0))) * uv0 * w;
                    float a1 = (gv1 / (1.f + expf(-gv1))) * uv1 * w;
                    __half2 hp = __floats2half2_rn(a0, a1);
                    int col = n0 + nc + nn * 8 + 2 * t4;
                    *(uint32_t*)&g_act_h[slot][col] = *(uint32_t*)&hp;
                }
            }
        }
    }
#undef GU_ISSUE
}

// ====== down GEMM: 256 thr, CTA 128x128, warps 4Mx2N (32x64), 3-stage =======
// stage: A[128][80]=10240 | B[128][80]=10240 ; STAGE 20480
#define DN_STAGE 20480
#define DN_META  (3 * DN_STAGE)
#define DN_SMEM  (DN_META + 512)
#define DN_NCH   (I_DIM / 32)

__global__ __launch_bounds__(256, 2) void down_mma_kernel(float* __restrict__ out) {
    int e = blockIdx.z;
    int cnt = g_cnt[e];
    int m0 = blockIdx.y * 128;
    if (m0 >= cnt) return;
    int base = g_off[e];
    int n0 = blockIdx.x * 128;

    extern __shared__ char smem[];
    uint32_t sb = smem_u32(smem);
    int tid = threadIdx.x, wid = tid >> 5, lane = tid & 31;
    int g = lane >> 2, t4 = lane & 3;
    int mr = (wid & 3) * 32, nc = (wid >> 2) * 64;

    int* stok = (int*)(smem + DN_META);
    if (tid < 128) {
        int r = m0 + tid;
        stok[tid] = (r < cnt) ? g_slot_tok[base + r] : 0;
    }
    __syncthreads();

    int lr = tid >> 1, asel = tid & 1;
    int arow_idx = base + min(m0 + lr, cnt - 1);
    const __half* a_src = &g_act_h[arow_idx][asel * 16];
    uint32_t aDst = sb + (uint32_t)(lr * 80 + asel * 32);
    const __half* b_src = g_wd_h + ((size_t)e * H_DIM + n0 + lr) * I_DIM + asel * 16;
    uint32_t bDst = sb + 10240u + (uint32_t)(lr * 80 + asel * 32);

    int quad = lane >> 3, r8 = lane & 7;
    int aRow = (quad & 1) * 8 + r8, aCol = (quad >> 1) * 8;
    int bRow = (quad >> 1) * 8 + r8, bCol = (quad & 1) * 8;
    uint32_t aBase = sb + (uint32_t)((mr + aRow) * 80 + aCol * 2);
    uint32_t bBase = sb + 10240u + (uint32_t)((nc + bRow) * 80 + bCol * 2);

    float acc[2][8][4] = {};   // warp 32x64: t in {0,1}, 8 n-frags of n8

#define DN_ISSUE(i) do { \
    uint32_t so = (uint32_t)((i) % 3) * DN_STAGE; \
    int k0 = (i) * 32; \
    CP16(aDst + so,      (const char*)(a_src + k0)); \
    CP16(aDst + so + 16, (const char*)(a_src + k0 + 8)); \
    CP16(bDst + so,      (const char*)(b_src + k0)); \
    CP16(bDst + so + 16, (const char*)(b_src + k0 + 8)); \
    CP_COMMIT(); \
} while (0)

    DN_ISSUE(0);
    DN_ISSUE(1);

    for (int i = 0; i < DN_NCH; i++) {
        if (i + 1 < DN_NCH) CP_WAIT1(); else CP_WAIT0();
        __syncthreads();
        if (i + 2 < DN_NCH) DN_ISSUE(i + 2);
        uint32_t so = (uint32_t)(i % 3) * DN_STAGE;
#pragma unroll
        for (int kb = 0; kb < 2; kb++) {
            uint32_t aF[2][4];
            uint32_t aA = aBase + so + kb * 32;
            LDMX4(aF[0], aA);
            LDMX4(aF[1], aA + 16 * 80);
#pragma unroll
            for (int u = 0; u < 4; u++) {
                uint32_t bF[4];
                LDMX4(bF, bBase + so + u * 1280 + kb * 32);
#pragma unroll
                for (int t = 0; t < 2; t++) {
                    mma16816(acc[t][2 * u + 0], aF[t], bF);
                    mma16816(acc[t][2 * u + 1], aF[t], bF + 2);
                }
            }
        }
        __syncthreads();
    }
#undef DN_ISSUE

    // epilogue: atomic accumulate
#pragma unroll
    for (int t = 0; t < 2; t++)
#pragma unroll
        for (int h = 0; h < 2; h++) {
            int lm = mr + t * 16 + g + h * 8;
            int r = m0 + lm;
            if (r < cnt) {
                int tok = stok[lm];
                float* orow = out + (size_t)tok * H_DIM + n0 + nc;
#pragma unroll
                for (int nn = 0; nn < 8; nn++) {
                    int col = nn * 8 + 2 * t4;
                    atomicAdd(&orow[col + 0], acc[t][nn][h * 2 + 0]);
                    atomicAdd(&orow[col + 1], acc[t][nn][h * 2 + 1]);
                }
            }
        }
}

// ---------------- launch ----------------
extern "C" void kernel_launch(void* const* d_in, const int* in_sizes, int n_in,
                              void* d_out, int out_size) {
    const float* hs    = (const float*)d_in[0];
    const float* gw    = (const float*)d_in[1];
    const float* wgate = (const float*)d_in[2];
    const float* wup   = (const float*)d_in[3];
    const float* wdown = (const float*)d_in[4];
    float* out = (float*)d_out;

    cudaFuncSetAttribute(gateup_mma_kernel, cudaFuncAttributeMaxDynamicSharedMemorySize, GU_SMEM);
    cudaFuncSetAttribute(down_mma_kernel,   cudaFuncAttributeMaxDynamicSharedMemorySize, DN_SMEM);

    cudaMemsetAsync(d_out, 0, (size_t)out_size * sizeof(float));
    conv_all_kernel<<<2048, 256>>>(wgate, wup, wdown, hs);
    router_kernel<<<T_TOK, 128>>>(hs, gw);
    scan_kernel<<<1, 32>>>();
    scatter_kernel<<<T_TOK / 256, 256>>>();
    gateup_mma_kernel<<<dim3(I_DIM / 64, T_TOK / 128, E_NUM), 256, GU_SMEM>>>();
    down_mma_kernel  <<<dim3(H_DIM / 128, T_TOK / 128, E_NUM), 256, DN_SMEM>>>(out);
}